// round 7
// baseline (speedup 1.0000x reference)
#include <cuda_runtime.h>
#include <math.h>

#define TT   512
#define DD   512
#define NTOK 1024          // B*T
#define NTH  256           // threads per block
#define NW   (NTH / 32)    // 8 warps
#define PROJ_TH 192        // 6 col-groups x 32 row-slices
#define ROWS_PER_TH 16     // 512 rows / 32 row-slices
#define SRS  33            // sred stride (odd: conflict-free column reads)

// 3-term Cody-Waite split of 2*pi (q*c1, q*c2 exact for q <= 4096; max q ~ 4083)
#define CW_C1      6.283203125f
#define CW_C2     -1.7821788788e-5f
#define CW_C3      3.968374e-9f
#define INV_2PI    0.15915494309189533576888376337251f

__device__ __forceinline__ float warp_sum(float v) {
    v += __shfl_down_sync(0xffffffffu, v, 16);
    v += __shfl_down_sync(0xffffffffu, v, 8);
    v += __shfl_down_sync(0xffffffffu, v, 4);
    v += __shfl_down_sync(0xffffffffu, v, 2);
    v += __shfl_down_sync(0xffffffffu, v, 1);
    return v;
}

__device__ __forceinline__ float emb_val(float r, float x, float scl, float shf) {
    float angle = __fmul_rn(r, x);
    float q  = rintf(angle * INV_2PI);
    float rf = fmaf(q, -CW_C1, angle);
    rf       = fmaf(q, -CW_C2, rf);
    rf       = fmaf(q, -CW_C3, rf);
    float sn = __sinf(rf);
    float cs = __cosf(rf);
    float comp = fmaf(cs, 1.f + sn, sn * sn);
    return fmaf(comp, scl, shf);
}

__global__ __launch_bounds__(NTH) void k_fused(
    const int*   __restrict__ token_ids,
    const float* __restrict__ resonances,
    const float* __restrict__ emb_scales,
    const float* __restrict__ emb_shifts,
    const float* __restrict__ emb_norm,
    const float* __restrict__ frac_norm,
    const float* __restrict__ W_enc,     // [512,24]
    const float* __restrict__ b_enc,     // [24]
    const float* __restrict__ W_dec,     // [24,512]
    const float* __restrict__ b_dec,     // [512]
    const float* __restrict__ ecc_strength,
    const float* __restrict__ energy_pres,
    float*       __restrict__ out)
{
    __shared__ float red[2][NW];
    __shared__ float se[2][DD];            // raw embeddings, 2 tokens
    __shared__ float sred[2][24 * SRS];    // proj partials [tok][k][r]
    __shared__ float sproj[2][24];
    __shared__ float slatt[2][12];
    __shared__ float scorr[2][24];
    __shared__ float s_ein2[2];

    const int tok0 = blockIdx.x * 2;
    const int tok1 = tok0 + 1;
    const int tid  = threadIdx.x;
    const int w    = tid >> 5;
    const int d0   = tid * 2;

    const float ep = energy_pres[0];

    // ---- embeddings for BOTH tokens (shared parameter loads) ----
    const float tv0 = __fdiv_rn((float)(token_ids[tok0] % 1000000), 1e6f);
    const float tv1 = __fdiv_rn((float)(token_ids[tok1] % 1000000), 1e6f);
    const float x0  = tv0 + (float)(tok0 & (TT - 1));
    const float x1  = tv1 + (float)(tok1 & (TT - 1));

    const float2 res2 = reinterpret_cast<const float2*>(resonances + d0)[0];
    const float2 scl2 = reinterpret_cast<const float2*>(emb_scales + d0)[0];
    const float2 shf2 = reinterpret_cast<const float2*>(emb_shifts + d0)[0];

    float2 e0, e1;
    e0.x = emb_val(res2.x, x0, scl2.x, shf2.x);
    e1.x = emb_val(res2.x, x1, scl2.x, shf2.x);
    e0.y = emb_val(res2.y, x0, scl2.y, shf2.y);
    e1.y = emb_val(res2.y, x1, scl2.y, shf2.y);
    reinterpret_cast<float2*>(se[0])[tid] = e0;
    reinterpret_cast<float2*>(se[1])[tid] = e1;
    float ss0 = fmaf(e0.x, e0.x, e0.y * e0.y);
    float ss1 = fmaf(e1.x, e1.x, e1.y * e1.y);
    float ws0 = warp_sum(ss0);
    float ws1 = warp_sum(ss1);
    if ((tid & 31) == 0) { red[0][w] = ws0; red[1][w] = ws1; }
    __syncthreads();                                    // S1

    // ---- proj partials: one coalesced W_enc sweep feeds BOTH tokens ----
    if (tid < PROJ_TH) {
        const int g = tid % 6;
        const int r = tid / 6;
        const float4* W4 = reinterpret_cast<const float4*>(W_enc);
        float a0 = 0.f, a1 = 0.f, a2 = 0.f, a3 = 0.f;
        float c0 = 0.f, c1 = 0.f, c2 = 0.f, c3 = 0.f;
        #pragma unroll
        for (int j = 0; j < ROWS_PER_TH; j++) {
            float4 wv = W4[tid + PROJ_TH * j];
            float v0 = se[0][r + 32 * j];
            float v1 = se[1][r + 32 * j];
            a0 = fmaf(v0, wv.x, a0); c0 = fmaf(v1, wv.x, c0);
            a1 = fmaf(v0, wv.y, a1); c1 = fmaf(v1, wv.y, c1);
            a2 = fmaf(v0, wv.z, a2); c2 = fmaf(v1, wv.z, c2);
            a3 = fmaf(v0, wv.w, a3); c3 = fmaf(v1, wv.w, c3);
        }
        const int kb = 4 * g;
        sred[0][(kb + 0) * SRS + r] = a0;
        sred[0][(kb + 1) * SRS + r] = a1;
        sred[0][(kb + 2) * SRS + r] = a2;
        sred[0][(kb + 3) * SRS + r] = a3;
        sred[1][(kb + 0) * SRS + r] = c0;
        sred[1][(kb + 1) * SRS + r] = c1;
        sred[1][(kb + 2) * SRS + r] = c2;
        sred[1][(kb + 3) * SRS + r] = c3;
    }
    __syncthreads();                                    // S2

    // ---- Golay pipeline: warp0 handles tok0, warp1 handles tok1 (parallel) ----
    if (tid < 64) {
        const int tk   = tid >> 5;
        const int lane = tid & 31;
        float tn2 = red[tk][0] + red[tk][1] + red[tk][2] + red[tk][3]
                  + red[tk][4] + red[tk][5] + red[tk][6] + red[tk][7];
        float tnorm = sqrtf(tn2);
        const float enorm = emb_norm[0];
        float sc_emb = (tnorm > 0.f) ? (enorm / tnorm) : 1.f;
        float e_in   = (tnorm > 0.f) ? enorm : 0.f;
        if (lane < 24) {
            float s = 0.f;
            #pragma unroll
            for (int q = 0; q < 32; q++) s += sred[tk][lane * SRS + q];
            sproj[tk][lane] = fmaf(sc_emb, s, b_enc[lane]);
        }
        __syncwarp();
        const float ecc = ecc_strength[0];
        const float* pj = sproj[tk];
        // G[i,l] = (l==i) + (12<=l<23)*((i+l-12)&1) + (l==23)*(i&1)
        float S_odd  = pj[13] + pj[15] + pj[17] + pj[19] + pj[21];
        float S_even = pj[12] + pj[14] + pj[16] + pj[18] + pj[20] + pj[22];
        float lat = 0.f, lsq = 0.f;
        if (lane < 12) {
            float ge = pj[lane] + ((lane & 1) ? (S_even + pj[23]) : S_odd);
            lat = rintf(__fdiv_rn(ge, ecc)) * ecc;      // round-half-even = jnp.round
            lsq = lat * lat;
        }
        float eout2 = warp_sum(lsq);
        eout2 = __shfl_sync(0xffffffffu, eout2, 0);
        float eout = sqrtf(eout2);
        float scl  = e_in / (eout + 1e-8f) * ep;
        if (lane < 12) slatt[tk][lane] = lat * scl;
        if (lane == 0) s_ein2[tk] = scl * eout;
        __syncwarp();
        const float* lt = slatt[tk];
        float L_odd  = lt[1] + lt[3] + lt[5] + lt[7] + lt[9] + lt[11];
        float L_even = lt[0] + lt[2] + lt[4] + lt[6] + lt[8] + lt[10];
        if (lane < 24) {
            float gd;
            if (lane < 12)      gd = lt[lane];
            else if (lane < 23) gd = ((lane - 12) & 1) ? L_even : L_odd;
            else                gd = L_odd;
            scorr[tk][lane] = (fabsf(gd) > ecc) ? gd : 0.f;
        }
    }
    __syncthreads();                                    // S3

    // ---- res = corrected @ W_dec + b_dec: one W_dec load feeds both tokens ----
    float2 bb = reinterpret_cast<const float2*>(b_dec)[tid];
    float2 rv0 = bb, rv1 = bb;
    #pragma unroll
    for (int l = 0; l < 24; l++) {
        const float c0 = scorr[0][l];
        const float c1 = scorr[1][l];
        float2 wv = reinterpret_cast<const float2*>(W_dec + l * DD)[tid];
        rv0.x = fmaf(c0, wv.x, rv0.x);  rv1.x = fmaf(c1, wv.x, rv1.x);
        rv0.y = fmaf(c0, wv.y, rv0.y);  rv1.y = fmaf(c1, wv.y, rv1.y);
    }
    float q0 = fmaf(rv0.x, rv0.x, rv0.y * rv0.y);
    float q1 = fmaf(rv1.x, rv1.x, rv1.y * rv1.y);
    float wq0 = warp_sum(q0);
    float wq1 = warp_sum(q1);
    if ((tid & 31) == 0) { red[0][w] = wq0; red[1][w] = wq1; }
    __syncthreads();                                    // S4
    float eo0 = sqrtf(red[0][0] + red[0][1] + red[0][2] + red[0][3]
                    + red[0][4] + red[0][5] + red[0][6] + red[0][7]);
    float eo1 = sqrtf(red[1][0] + red[1][1] + red[1][2] + red[1][3]
                    + red[1][4] + red[1][5] + red[1][6] + red[1][7]);
    // global fractal factor folds in analytically: f = frac_norm*32*emb_norm*ep^2
    const float fglob = frac_norm[0] * 32.0f * emb_norm[0] * ep * ep;
    float sf0 = s_ein2[0] / (eo0 + 1e-8f) * ep * fglob;
    float sf1 = s_ein2[1] / (eo1 + 1e-8f) * ep * fglob;
    rv0.x *= sf0; rv0.y *= sf0;
    rv1.x *= sf1; rv1.y *= sf1;
    reinterpret_cast<float2*>(out + tok0 * DD)[tid] = rv0;
    reinterpret_cast<float2*>(out + tok1 * DD)[tid] = rv1;
}

extern "C" void kernel_launch(void* const* d_in, const int* in_sizes, int n_in,
                              void* d_out, int out_size) {
    (void)in_sizes; (void)n_in; (void)out_size;
    const int*   token_ids    = (const int*)  d_in[0];
    const float* resonances   = (const float*)d_in[1];
    const float* emb_scales   = (const float*)d_in[2];
    const float* emb_shifts   = (const float*)d_in[3];
    const float* emb_norm     = (const float*)d_in[4];
    // d_in[5] scale_weights, d_in[6] fractal_bias: cancel exactly in the math
    const float* frac_norm    = (const float*)d_in[7];
    const float* W_enc        = (const float*)d_in[8];
    const float* b_enc        = (const float*)d_in[9];
    const float* W_dec        = (const float*)d_in[10];
    const float* b_dec        = (const float*)d_in[11];
    const float* ecc_strength = (const float*)d_in[12];
    const float* energy_pres  = (const float*)d_in[13];
    float* out = (float*)d_out;

    k_fused<<<NTOK / 2, NTH>>>(token_ids, resonances, emb_scales, emb_shifts, emb_norm,
                               frac_norm, W_enc, b_enc, W_dec, b_dec,
                               ecc_strength, energy_pres, out);
}

// round 8
// speedup vs baseline: 1.3325x; 1.3325x over previous
#include <cuda_runtime.h>
#include <math.h>

#define TT   512
#define DD   512
#define NTOK 1024          // B*T
#define NTH  256           // threads per token-block
#define CPT  2             // d-values per thread (NTH*CPT = DD)
#define NW   (NTH / 32)    // 8 warps
#define PROJ_TH 192        // 6 col-groups x 32 row-slices
#define ROWS_PER_TH 16     // 512 rows / 32 row-slices
#define SRS  33            // sred stride (odd: conflict-free column reads)

// 3-term Cody-Waite split of 2*pi (q*c1, q*c2 exact for q <= 4096; max q ~ 4083)
#define CW_C1      6.283203125f
#define CW_C2     -1.7821788788e-5f
#define CW_C3      3.968374e-9f
#define INV_2PI    0.15915494309189533576888376337251f

__device__ __forceinline__ float warp_sum(float v) {
    v += __shfl_down_sync(0xffffffffu, v, 16);
    v += __shfl_down_sync(0xffffffffu, v, 8);
    v += __shfl_down_sync(0xffffffffu, v, 4);
    v += __shfl_down_sync(0xffffffffu, v, 2);
    v += __shfl_down_sync(0xffffffffu, v, 1);
    return v;
}

__device__ __forceinline__ float tree8(const float* r) {
    float a = r[0] + r[1], b = r[2] + r[3], c = r[4] + r[5], d = r[6] + r[7];
    return (a + b) + (c + d);
}

__global__ __launch_bounds__(NTH, 4) void k_fused(
    const int*   __restrict__ token_ids,
    const float* __restrict__ resonances,
    const float* __restrict__ emb_scales,
    const float* __restrict__ emb_shifts,
    const float* __restrict__ emb_norm,
    const float* __restrict__ frac_norm,
    const float* __restrict__ W_enc,     // [512,24]
    const float* __restrict__ b_enc,     // [24]
    const float* __restrict__ W_dec,     // [24,512]
    const float* __restrict__ b_dec,     // [512]
    const float* __restrict__ ecc_strength,
    const float* __restrict__ energy_pres,
    float*       __restrict__ out)
{
    __shared__ float red[NW];
    __shared__ float se[DD];                 // raw embedding
    __shared__ float sred[24 * SRS];         // proj partials [k][r-slice], padded
    __shared__ float sproj[24];
    __shared__ float slatt[12];
    __shared__ float scorr[24];
    __shared__ float s_ein2;

    const int tok = blockIdx.x;          // b*T + t
    const int t   = tok & (TT - 1);
    const int tid = threadIdx.x;
    const int w   = tid >> 5;
    const int d0  = tid * CPT;

    const float ep = energy_pres[0];

    // ---- embedding (raw; normalization deferred past the proj reduction) ----
    const int   id = token_ids[tok];
    const float tv = __fdiv_rn((float)(id % 1000000), 1e6f);
    const float x  = tv + (float)t;

    const float2 res2 = reinterpret_cast<const float2*>(resonances + d0)[0];
    const float2 scl2v= reinterpret_cast<const float2*>(emb_scales + d0)[0];
    const float2 shf2 = reinterpret_cast<const float2*>(emb_shifts + d0)[0];
    const float rr[CPT] = {res2.x, res2.y};
    const float sl[CPT] = {scl2v.x, scl2v.y};
    const float sh[CPT] = {shf2.x, shf2.y};

    float2 ev2;
    float ss = 0.f;
    {
        float ebuf[CPT];
        #pragma unroll
        for (int i = 0; i < CPT; i++) {
            float angle = __fmul_rn(rr[i], x);
            float q  = rintf(angle * INV_2PI);
            float rf = fmaf(q, -CW_C1, angle);
            rf       = fmaf(q, -CW_C2, rf);
            rf       = fmaf(q, -CW_C3, rf);
            float sn = __sinf(rf);
            float cs = __cosf(rf);
            float comp = fmaf(cs, 1.f + sn, sn * sn);
            float v = fmaf(comp, sl[i], sh[i]);
            ebuf[i] = v;
            ss = fmaf(v, v, ss);
        }
        ev2.x = ebuf[0]; ev2.y = ebuf[1];
    }
    reinterpret_cast<float2*>(se)[tid] = ev2;
    float wss = warp_sum(ss);
    if ((tid & 31) == 0) red[w] = wss;
    __syncthreads();                                    // S1: se + norm partials ready

    // ---- proj partials: fully-coalesced W_enc sweep (192 threads) ----
    // W_enc viewed as 3072 float4s; iter j loads 192 consecutive float4s.
    if (tid < PROJ_TH) {
        const int g = tid % 6;
        const int r = tid / 6;
        const float4* W4 = reinterpret_cast<const float4*>(W_enc);
        float p0 = 0.f, p1 = 0.f, p2 = 0.f, p3 = 0.f;
        #pragma unroll
        for (int j = 0; j < ROWS_PER_TH; j++) {
            float4 wv = W4[tid + PROJ_TH * j];
            float evr = se[r + 32 * j];              // broadcast, conflict-free
            p0 = fmaf(evr, wv.x, p0);
            p1 = fmaf(evr, wv.y, p1);
            p2 = fmaf(evr, wv.z, p2);
            p3 = fmaf(evr, wv.w, p3);
        }
        const int kb = 4 * g;
        sred[(kb + 0) * SRS + r] = p0;
        sred[(kb + 1) * SRS + r] = p1;
        sred[(kb + 2) * SRS + r] = p2;
        sred[(kb + 3) * SRS + r] = p3;
    }
    __syncthreads();                                    // S2

    // ---- norm-apply + proj reduce + Golay enc/round/rescale/dec/threshold: ONE warp ----
    if (tid < 32) {
        float tn2 = tree8(red);
        float tnorm = sqrtf(tn2);
        const float enorm = emb_norm[0];
        const float ecc   = ecc_strength[0];
        float sc_emb = (tnorm > 0.f) ? (enorm / tnorm) : 1.f;
        float e_in   = (tnorm > 0.f) ? enorm : 0.f;     // == tnorm*sc_emb
        if (tid < 24) {
            // 4 independent accumulators: breaks the 32-deep serial FADD chain
            const float* sr = sred + tid * SRS;
            float a0 = 0.f, a1 = 0.f, a2 = 0.f, a3 = 0.f;
            #pragma unroll
            for (int q = 0; q < 32; q += 4) {
                a0 += sr[q + 0];
                a1 += sr[q + 1];
                a2 += sr[q + 2];
                a3 += sr[q + 3];
            }
            sproj[tid] = fmaf(sc_emb, (a0 + a1) + (a2 + a3), b_enc[tid]);
        }
        __syncwarp();
        // G[i,l] = (l==i) + (12<=l<23)*((i+l-12)&1) + (l==23)*(i&1)
        float S_odd  = (sproj[13] + sproj[15]) + (sproj[17] + sproj[19]) + sproj[21];
        float S_even = (sproj[12] + sproj[14]) + (sproj[16] + sproj[18]) + (sproj[20] + sproj[22]);
        float lat = 0.f, lsq = 0.f;
        if (tid < 12) {
            float ge = sproj[tid] + ((tid & 1) ? (S_even + sproj[23]) : S_odd);
            lat = rintf(__fdiv_rn(ge, ecc)) * ecc;      // round-half-even = jnp.round
            lsq = lat * lat;
        }
        float eout2 = warp_sum(lsq);
        eout2 = __shfl_sync(0xffffffffu, eout2, 0);
        float eout = sqrtf(eout2);
        float scl  = e_in / (eout + 1e-8f) * ep;
        if (tid < 12) slatt[tid] = lat * scl;
        if (tid == 0) s_ein2 = scl * eout;              // ||latt|| after scaling
        __syncwarp();
        float L_odd  = (slatt[1] + slatt[3]) + (slatt[5] + slatt[7]) + (slatt[9] + slatt[11]);
        float L_even = (slatt[0] + slatt[2]) + (slatt[4] + slatt[6]) + (slatt[8] + slatt[10]);
        if (tid < 24) {
            float gd;
            if (tid < 12)      gd = slatt[tid];
            else if (tid < 23) gd = ((tid - 12) & 1) ? L_even : L_odd;
            else               gd = L_odd;
            scorr[tid] = (fabsf(gd) > ecc) ? gd : 0.f;
        }
    }
    __syncthreads();                                    // S3

    // ---- res = corrected @ W_dec + b_dec (coalesced; batched independent loads) ----
    float2 rv = reinterpret_cast<const float2*>(b_dec)[tid];
    {
        float2 racc = {0.f, 0.f};
        #pragma unroll
        for (int lb = 0; lb < 24; lb += 8) {
            float2 wv[8];
            #pragma unroll
            for (int u = 0; u < 8; u++)
                wv[u] = reinterpret_cast<const float2*>(W_dec + (lb + u) * DD)[tid];
            #pragma unroll
            for (int u = 0; u < 8; u++) {
                const float c = scorr[lb + u];
                rv.x   = fmaf(c, wv[u].x, rv.x);
                racc.y = fmaf(c, wv[u].y, racc.y);   // second independent chain
            }
        }
        rv.y += racc.y;
    }
    float ss2 = fmaf(rv.x, rv.x, rv.y * rv.y);
    float wss2 = warp_sum(ss2);
    if ((tid & 31) == 0) red[w] = wss2;
    __syncthreads();                                    // S4
    float eo2 = sqrtf(tree8(red));
    // global fractal factor folds in analytically: f = frac_norm*32*emb_norm*ep^2
    const float fglob = frac_norm[0] * 32.0f * emb_norm[0] * ep * ep;
    float sfin  = s_ein2 / (eo2 + 1e-8f) * ep * fglob;
    rv.x *= sfin; rv.y *= sfin;
    reinterpret_cast<float2*>(out + tok * DD)[tid] = rv;
}

extern "C" void kernel_launch(void* const* d_in, const int* in_sizes, int n_in,
                              void* d_out, int out_size) {
    (void)in_sizes; (void)n_in; (void)out_size;
    const int*   token_ids    = (const int*)  d_in[0];
    const float* resonances   = (const float*)d_in[1];
    const float* emb_scales   = (const float*)d_in[2];
    const float* emb_shifts   = (const float*)d_in[3];
    const float* emb_norm     = (const float*)d_in[4];
    // d_in[5] scale_weights, d_in[6] fractal_bias: cancel exactly in the math
    const float* frac_norm    = (const float*)d_in[7];
    const float* W_enc        = (const float*)d_in[8];
    const float* b_enc        = (const float*)d_in[9];
    const float* W_dec        = (const float*)d_in[10];
    const float* b_dec        = (const float*)d_in[11];
    const float* ecc_strength = (const float*)d_in[12];
    const float* energy_pres  = (const float*)d_in[13];
    float* out = (float*)d_out;

    k_fused<<<NTOK, NTH>>>(token_ids, resonances, emb_scales, emb_shifts, emb_norm,
                           frac_norm, W_enc, b_enc, W_dec, b_dec,
                           ecc_strength, energy_pres, out);
}

// round 11
// speedup vs baseline: 1.6698x; 1.2531x over previous
#include <cuda_runtime.h>
#include <math.h>

#define TT   512
#define DD   512
#define NTOK 1024          // B*T
#define NTH  256           // threads per token-block
#define CPT  2             // d-values per thread (NTH*CPT = DD)
#define NW   (NTH / 32)    // 8 warps
#define PROJ_TH 192        // 6 col-groups x 32 row-slices
#define ROWS_PER_TH 16     // 512 rows / 32 row-slices
#define SRS  33            // sred stride (odd: conflict-free column reads)

// 3-term Cody-Waite split of 2*pi (q*c1, q*c2 exact for q <= 4096; max q ~ 4083)
#define CW_C1      6.283203125f
#define CW_C2     -1.7821788788e-5f
#define CW_C3      3.968374e-9f
#define INV_2PI    0.15915494309189533576888376337251f

__device__ __forceinline__ float warp_sum(float v) {
    v += __shfl_down_sync(0xffffffffu, v, 16);
    v += __shfl_down_sync(0xffffffffu, v, 8);
    v += __shfl_down_sync(0xffffffffu, v, 4);
    v += __shfl_down_sync(0xffffffffu, v, 2);
    v += __shfl_down_sync(0xffffffffu, v, 1);
    return v;
}

__device__ __forceinline__ float tree8(const float* r) {
    float a = r[0] + r[1], b = r[2] + r[3], c = r[4] + r[5], d = r[6] + r[7];
    return (a + b) + (c + d);
}

__global__ __launch_bounds__(NTH, 7) void k_fused(
    const int*   __restrict__ token_ids,
    const float* __restrict__ resonances,
    const float* __restrict__ emb_scales,
    const float* __restrict__ emb_shifts,
    const float* __restrict__ emb_norm,
    const float* __restrict__ frac_norm,
    const float* __restrict__ W_enc,     // [512,24]
    const float* __restrict__ b_enc,     // [24]
    const float* __restrict__ W_dec,     // [24,512]
    const float* __restrict__ b_dec,     // [512]
    const float* __restrict__ ecc_strength,
    const float* __restrict__ energy_pres,
    float*       __restrict__ out)
{
    __shared__ float red[NW];
    __shared__ float se[DD];                 // raw embedding
    __shared__ float sred[24 * SRS];         // proj partials [k][r-slice], padded
    __shared__ float sproj[24];
    __shared__ float slatt[12];
    __shared__ float scorr[24];
    __shared__ float s_ein2;

    const int tok = blockIdx.x;          // b*T + t
    const int t   = tok & (TT - 1);
    const int tid = threadIdx.x;
    const int w   = tid >> 5;
    const int d0  = tid * CPT;

    const float ep = energy_pres[0];

    // ---- embedding (raw; normalization deferred past the proj reduction) ----
    const int   id = token_ids[tok];
    const float tv = __fdiv_rn((float)(id % 1000000), 1e6f);
    const float x  = tv + (float)t;

    const float2 res2 = reinterpret_cast<const float2*>(resonances + d0)[0];
    const float2 scl2v= reinterpret_cast<const float2*>(emb_scales + d0)[0];
    const float2 shf2 = reinterpret_cast<const float2*>(emb_shifts + d0)[0];
    const float rr[CPT] = {res2.x, res2.y};
    const float sl[CPT] = {scl2v.x, scl2v.y};
    const float sh[CPT] = {shf2.x, shf2.y};

    float2 ev2;
    float ss = 0.f;
    {
        float ebuf[CPT];
        #pragma unroll
        for (int i = 0; i < CPT; i++) {
            float angle = __fmul_rn(rr[i], x);
            float q  = rintf(angle * INV_2PI);
            float rf = fmaf(q, -CW_C1, angle);
            rf       = fmaf(q, -CW_C2, rf);
            rf       = fmaf(q, -CW_C3, rf);
            float sn = __sinf(rf);
            float cs = __cosf(rf);
            float comp = fmaf(cs, 1.f + sn, sn * sn);
            float v = fmaf(comp, sl[i], sh[i]);
            ebuf[i] = v;
            ss = fmaf(v, v, ss);
        }
        ev2.x = ebuf[0]; ev2.y = ebuf[1];
    }
    reinterpret_cast<float2*>(se)[tid] = ev2;
    float wss = warp_sum(ss);
    if ((tid & 31) == 0) red[w] = wss;
    __syncthreads();                                    // S1: se + norm partials ready

    // ---- proj partials: fully-coalesced W_enc sweep (192 threads) ----
    // W_enc viewed as 3072 float4s; iter j loads 192 consecutive float4s.
    if (tid < PROJ_TH) {
        const int g = tid % 6;
        const int r = tid / 6;
        const float4* W4 = reinterpret_cast<const float4*>(W_enc);
        float p0 = 0.f, p1 = 0.f, p2 = 0.f, p3 = 0.f;
        #pragma unroll
        for (int j = 0; j < ROWS_PER_TH; j++) {
            float4 wv = W4[tid + PROJ_TH * j];
            float evr = se[r + 32 * j];              // broadcast, conflict-free
            p0 = fmaf(evr, wv.x, p0);
            p1 = fmaf(evr, wv.y, p1);
            p2 = fmaf(evr, wv.z, p2);
            p3 = fmaf(evr, wv.w, p3);
        }
        const int kb = 4 * g;
        sred[(kb + 0) * SRS + r] = p0;
        sred[(kb + 1) * SRS + r] = p1;
        sred[(kb + 2) * SRS + r] = p2;
        sred[(kb + 3) * SRS + r] = p3;
    }
    __syncthreads();                                    // S2

    // ---- norm-apply + proj reduce + Golay enc/round/rescale/dec/threshold: ONE warp ----
    if (tid < 32) {
        // scalar prefetch first: LDG latency overlaps the LDS reduce below
        const float enorm = emb_norm[0];
        const float ecc   = ecc_strength[0];
        const float be    = (tid < 24) ? b_enc[tid] : 0.f;
        float tn2 = tree8(red);
        float tnorm = sqrtf(tn2);
        float sc_emb = (tnorm > 0.f) ? (enorm / tnorm) : 1.f;
        float e_in   = (tnorm > 0.f) ? enorm : 0.f;     // == tnorm*sc_emb
        if (tid < 24) {
            // 4 independent accumulators: breaks the 32-deep serial FADD chain
            const float* sr = sred + tid * SRS;
            float a0 = 0.f, a1 = 0.f, a2 = 0.f, a3 = 0.f;
            #pragma unroll
            for (int q = 0; q < 32; q += 4) {
                a0 += sr[q + 0];
                a1 += sr[q + 1];
                a2 += sr[q + 2];
                a3 += sr[q + 3];
            }
            sproj[tid] = fmaf(sc_emb, (a0 + a1) + (a2 + a3), be);
        }
        __syncwarp();
        // G[i,l] = (l==i) + (12<=l<23)*((i+l-12)&1) + (l==23)*(i&1)
        float S_odd  = (sproj[13] + sproj[15]) + (sproj[17] + sproj[19]) + sproj[21];
        float S_even = (sproj[12] + sproj[14]) + (sproj[16] + sproj[18]) + (sproj[20] + sproj[22]);
        float lat = 0.f, lsq = 0.f;
        if (tid < 12) {
            float ge = sproj[tid] + ((tid & 1) ? (S_even + sproj[23]) : S_odd);
            lat = rintf(__fdiv_rn(ge, ecc)) * ecc;      // round-half-even = jnp.round
            lsq = lat * lat;
        }
        float eout2 = warp_sum(lsq);
        eout2 = __shfl_sync(0xffffffffu, eout2, 0);
        float eout = sqrtf(eout2);
        float scl  = e_in / (eout + 1e-8f) * ep;
        if (tid < 12) slatt[tid] = lat * scl;
        if (tid == 0) s_ein2 = scl * eout;              // ||latt|| after scaling
        __syncwarp();
        float L_odd  = (slatt[1] + slatt[3]) + (slatt[5] + slatt[7]) + (slatt[9] + slatt[11]);
        float L_even = (slatt[0] + slatt[2]) + (slatt[4] + slatt[6]) + (slatt[8] + slatt[10]);
        if (tid < 24) {
            float gd;
            if (tid < 12)      gd = slatt[tid];
            else if (tid < 23) gd = ((tid - 12) & 1) ? L_even : L_odd;
            else               gd = L_odd;
            scorr[tid] = (fabsf(gd) > ecc) ? gd : 0.f;
        }
    }
    __syncthreads();                                    // S3

    // ---- res = corrected @ W_dec + b_dec  (coalesced float2 on d; R5 form) ----
    float2 rv = reinterpret_cast<const float2*>(b_dec)[tid];
    #pragma unroll
    for (int l = 0; l < 24; l++) {
        const float c = scorr[l];
        float2 wv = reinterpret_cast<const float2*>(W_dec + l * DD)[tid];
        rv.x = fmaf(c, wv.x, rv.x);
        rv.y = fmaf(c, wv.y, rv.y);
    }
    float ss2 = fmaf(rv.x, rv.x, rv.y * rv.y);
    float wss2 = warp_sum(ss2);
    if ((tid & 31) == 0) red[w] = wss2;
    __syncthreads();                                    // S4
    float eo2 = sqrtf(tree8(red));
    // global fractal factor folds in analytically: f = frac_norm*32*emb_norm*ep^2
    const float fglob = frac_norm[0] * 32.0f * emb_norm[0] * ep * ep;
    float sfin  = s_ein2 / (eo2 + 1e-8f) * ep * fglob;
    rv.x *= sfin; rv.y *= sfin;
    reinterpret_cast<float2*>(out + tok * DD)[tid] = rv;
}

extern "C" void kernel_launch(void* const* d_in, const int* in_sizes, int n_in,
                              void* d_out, int out_size) {
    (void)in_sizes; (void)n_in; (void)out_size;
    const int*   token_ids    = (const int*)  d_in[0];
    const float* resonances   = (const float*)d_in[1];
    const float* emb_scales   = (const float*)d_in[2];
    const float* emb_shifts   = (const float*)d_in[3];
    const float* emb_norm     = (const float*)d_in[4];
    // d_in[5] scale_weights, d_in[6] fractal_bias: cancel exactly in the math
    const float* frac_norm    = (const float*)d_in[7];
    const float* W_enc        = (const float*)d_in[8];
    const float* b_enc        = (const float*)d_in[9];
    const float* W_dec        = (const float*)d_in[10];
    const float* b_dec        = (const float*)d_in[11];
    const float* ecc_strength = (const float*)d_in[12];
    const float* energy_pres  = (const float*)d_in[13];
    float* out = (float*)d_out;

    k_fused<<<NTOK, NTH>>>(token_ids, resonances, emb_scales, emb_shifts, emb_norm,
                           frac_norm, W_enc, b_enc, W_dec, b_dec,
                           ecc_strength, energy_pres, out);
}